// round 5
// baseline (speedup 1.0000x reference)
#include <cuda_runtime.h>
#include <cstdint>

// ---------------- problem dims ----------------
static constexpr int NE   = 8;
static constexpr int TOKN = 1024;
static constexpr int HID  = 2048;
static constexpr int ITR  = 6144;

static constexpr int BM = 128;   // CTA M tile
static constexpr int BK = 16;    // K chunk per pipeline stage
static constexpr int AP = 20;    // padded A row stride in floats (bank-conflict-free)

// fp32 intermediate activations (no cudaMalloc allowed -> static device scratch)
__device__ float g_hidden[(size_t)NE * TOKN * ITR];

// ---------------- ptx helpers (baseline PTX only: sm_80-era features) ----------------
__device__ __forceinline__ void cp16(void* dst_smem, const void* src) {
    uint32_t d = (uint32_t)__cvta_generic_to_shared(dst_smem);
    asm volatile("cp.async.cg.shared.global [%0], [%1], 16;\n" :: "r"(d), "l"(src));
}
__device__ __forceinline__ void cp_commit() {
    asm volatile("cp.async.commit_group;\n" ::: "memory");
}
template <int N>
__device__ __forceinline__ void cp_wait() {
    asm volatile("cp.async.wait_group %0;\n" :: "n"(N) : "memory");
}
__device__ __forceinline__ uint32_t f2tf(float f) {
    uint32_t r;
    asm("cvt.rna.tf32.f32 %0, %1;\n" : "=r"(r) : "f"(f));
    return r;
}
// D += A*B, m16n8k8 tf32 (A row-major, B col-major fragments)
__device__ __forceinline__ void mma_tf32(float* c, const uint32_t* a, const uint32_t* b) {
    asm volatile(
        "mma.sync.aligned.m16n8k8.row.col.f32.tf32.tf32.f32 "
        "{%0,%1,%2,%3}, {%4,%5,%6,%7}, {%8,%9}, {%0,%1,%2,%3};\n"
        : "+f"(c[0]), "+f"(c[1]), "+f"(c[2]), "+f"(c[3])
        : "r"(a[0]), "r"(a[1]), "r"(a[2]), "r"(a[3]), "r"(b[0]), "r"(b[1]));
}

// ---------------- GEMM kernel ----------------
// D[M,N] = A[M,K] * B[K,N].  A is K-contiguous, B is N-contiguous (row-major [K,N]).
// FUSED: two B streams (gate @ n0, up @ n0+ITR within the same weight tensor),
//        epilogue = silu(gate)*up.
template <int BNS, bool FUSED>
__global__ __launch_bounds__(256)
void moe_mma_kernel(const float* __restrict__ Ag,
                    const float* __restrict__ Bg,
                    float* __restrict__ Og,
                    int K, int bstride, int ostride, int kiter) {
    constexpr int NSTR = FUSED ? 2 : 1;
    constexpr int BP   = BNS + 8;         // padded B row stride (floats)
    constexpr int NJ   = BNS / 16;        // n-tiles (of 8) per warp per stream
    constexpr int BCH  = BK * BNS / 4;    // float4 chunks per B tile per stream
    constexpr int NBL  = BCH / 256;       // B chunks per thread (1 or 2)

    __shared__ float As[2][BM * AP];
    __shared__ float Bs[NSTR][2][BK * BP];

    const int tid  = threadIdx.x;
    const int wid  = tid >> 5, lane = tid & 31;
    const int g    = lane >> 2, t = lane & 3;
    const int wm   = wid >> 1, wn = wid & 1;

    const int e  = blockIdx.z;
    const int m0 = blockIdx.y * BM;
    const int n0 = blockIdx.x * BNS;

    const float* A  = Ag + ((size_t)e * TOKN + m0) * K;
    const float* B0 = Bg + (size_t)e * K * bstride + n0;
    const float* B1 = FUSED ? (B0 + ITR) : B0;
    float*       O  = Og + ((size_t)e * TOKN + m0) * ostride + n0;

    // ---- per-thread load maps ----
    // A tile: 128x16 floats = 512 float4 chunks; thread does chunks tid, tid+256
    const int ar0 = tid >> 1;                 // chunk c=tid      : row = c>>2 ... recompute exactly:
    // chunk c: row = c>>2, col4 = (c&3)*4
    const int ac0r = tid >> 2,        ac0c = (tid & 3) * 4;
    const int ac1r = (tid + 256) >> 2, ac1c = ((tid + 256) & 3) * 4;
    (void)ar0;
    const float* Asrc0 = A + (size_t)ac0r * K + ac0c;
    const float* Asrc1 = A + (size_t)ac1r * K + ac1c;

    // B tile: BK x BNS floats per stream; chunk c: row = c/(BNS/4), col4 = (c%(BNS/4))*4
    int brow[NBL], bcol[NBL];
#pragma unroll
    for (int i = 0; i < NBL; ++i) {
        int c = tid + i * 256;
        brow[i] = c / (BNS / 4);
        bcol[i] = (c % (BNS / 4)) * 4;
    }

    auto load_tiles = [&](int buf, int kc) {
        cp16(&As[buf][ac0r * AP + ac0c], Asrc0 + (size_t)kc * BK);
        cp16(&As[buf][ac1r * AP + ac1c], Asrc1 + (size_t)kc * BK);
#pragma unroll
        for (int i = 0; i < NBL; ++i) {
            size_t go = ((size_t)(kc * BK + brow[i])) * bstride + bcol[i];
            cp16(&Bs[0][buf][brow[i] * BP + bcol[i]], B0 + go);
            if (FUSED)
                cp16(&Bs[1][buf][brow[i] * BP + bcol[i]], B1 + go);
        }
        cp_commit();
    };

    float acc[NSTR][2][NJ][4] = {};

    // ---- pipeline ----
    load_tiles(0, 0);

    for (int c = 0; c < kiter; ++c) {
        const int cur = c & 1;
        if (c + 1 < kiter) {
            load_tiles(cur ^ 1, c + 1);
            cp_wait<1>();
        } else {
            cp_wait<0>();
        }
        __syncthreads();

#pragma unroll
        for (int ks = 0; ks < 2; ++ks) {
            const int kb = ks * 8;
            uint32_t af[2][4];
#pragma unroll
            for (int mi = 0; mi < 2; ++mi) {
                const float* Ar = &As[cur][(wm * 32 + mi * 16 + g) * AP + kb + t];
                af[mi][0] = f2tf(Ar[0]);
                af[mi][1] = f2tf(Ar[8 * AP]);
                af[mi][2] = f2tf(Ar[4]);
                af[mi][3] = f2tf(Ar[8 * AP + 4]);
            }
#pragma unroll
            for (int s = 0; s < NSTR; ++s) {
                uint32_t bf[NJ][2];
#pragma unroll
                for (int nj = 0; nj < NJ; ++nj) {
                    const float* Br = &Bs[s][cur][(kb + t) * BP + wn * (BNS / 2) + nj * 8 + g];
                    bf[nj][0] = f2tf(Br[0]);
                    bf[nj][1] = f2tf(Br[4 * BP]);
                }
#pragma unroll
                for (int mi = 0; mi < 2; ++mi)
#pragma unroll
                    for (int nj = 0; nj < NJ; ++nj)
                        mma_tf32(acc[s][mi][nj], af[mi], bf[nj]);
            }
        }
        __syncthreads();
    }

    // ---- epilogue ----
#pragma unroll
    for (int mi = 0; mi < 2; ++mi) {
#pragma unroll
        for (int h = 0; h < 2; ++h) {
            const int row = wm * 32 + mi * 16 + g + h * 8;
            float* orow = O + (size_t)row * ostride + wn * (BNS / 2);
#pragma unroll
            for (int nj = 0; nj < NJ; ++nj) {
                const int col = nj * 8 + 2 * t;
                float2 v;
                if (FUSED) {
                    float g0 = acc[0][mi][nj][2 * h],     u0 = acc[1][mi][nj][2 * h];
                    float g1 = acc[0][mi][nj][2 * h + 1], u1 = acc[1][mi][nj][2 * h + 1];
                    v.x = g0 / (1.0f + __expf(-g0)) * u0;   // silu(gate)*up
                    v.y = g1 / (1.0f + __expf(-g1)) * u1;
                } else {
                    v.x = acc[0][mi][nj][2 * h];
                    v.y = acc[0][mi][nj][2 * h + 1];
                }
                *reinterpret_cast<float2*>(orow + col) = v;
            }
        }
    }
}

// ---------------- launch ----------------
extern "C" void kernel_launch(void* const* d_in, const int* in_sizes, int n_in,
                              void* d_out, int out_size) {
    (void)in_sizes; (void)n_in; (void)out_size;
    const float* x   = (const float*)d_in[0];   // [E*T, D]
    const float* wgu = (const float*)d_in[1];   // [E, D, 2I]
    const float* wdn = (const float*)d_in[2];   // [E, I, D]
    float* out = (float*)d_out;                 // [E*T, D]

    float* hid = nullptr;
    cudaGetSymbolAddress((void**)&hid, g_hidden);

    // stage 1: gate_up GEMM + silu*up fused epilogue -> g_hidden [E,T,I]
    moe_mma_kernel<64, true><<<dim3(ITR / 64, TOKN / BM, NE), 256>>>(
        x, wgu, hid, HID, 2 * ITR, ITR, HID / BK);
    // stage 2: down GEMM -> out [E,T,D]
    moe_mma_kernel<128, false><<<dim3(HID / 128, TOKN / BM, NE), 256>>>(
        hid, wdn, out, ITR, HID, HID, ITR / BK);
}